// round 3
// baseline (speedup 1.0000x reference)
#include <cuda_runtime.h>

// Problem constants
#define BB   32
#define DD   384
#define TTOT 4096
#define KK   256
#define TT   64            // t-tile per block
#define DC   16            // d-chunk
#define NCH  (DD / DC)     // 24 chunks
#define TAU  1e-2f         // near-tie screening margin
#define MAXF 32768         // max flagged points

// Output layout: quantize [B,D,T] | indices [B,T] (as float) | loss (1 float)
#define Q_ELEMS   ((size_t)BB * DD * TTOT)
#define IDX_ELEMS ((size_t)BB * TTOT)

// Scratch (no cudaMalloc allowed)
__device__ float  g_ct[DD * KK];        // transposed codebook ct[d][k]
__device__ float  g_e2f[KK];            // ||c_k||^2, XLA-emulated fp32 rounding
__device__ int    g_idx[BB * TTOT];     // chosen code per point
__device__ float  g_partials[512];      // per-block loss partials
__device__ int    g_nflag;              // flagged-point count
__device__ int    g_fpt[MAXF];          // packed (b<<12)|t
__device__ int    g_fcnt[MAXF];         // candidate count (-1 => scan all 256)
__device__ int    g_fcand[MAXF][8];     // candidate code ids (slot 0 = screening best)

// ---- packed f32x2 helpers (Blackwell FFMA2) ----
__device__ __forceinline__ unsigned long long pack2(float x) {
    unsigned long long r;
    unsigned u = __float_as_uint(x);
    asm("mov.b64 %0, {%1, %1};" : "=l"(r) : "r"(u));
    return r;
}
__device__ __forceinline__ void ffma2(unsigned long long& d,
                                      unsigned long long a,
                                      unsigned long long b) {
    asm("fma.rn.f32x2 %0, %1, %2, %0;" : "+l"(d) : "l"(a), "l"(b));
}
__device__ __forceinline__ float lo32(unsigned long long v) {
    return __uint_as_float((unsigned)(v & 0xffffffffULL));
}
__device__ __forceinline__ float hi32(unsigned long long v) {
    return __uint_as_float((unsigned)(v >> 32));
}

// ---- prep: transpose codebook + XLA-emulated e2 + reset flag counter ----
// blocks [0,384): transpose; [384,416): e2 rows, one warp per row; 416: reset
__global__ void vq_prep(const float* __restrict__ cb) {
    const unsigned FULL = 0xffffffffu;
    int bid = blockIdx.x;
    if (bid < (KK * DD) / 256) {
        int gid = bid * 256 + threadIdx.x;
        int k = gid / DD;
        int d = gid - k * DD;
        g_ct[d * KK + k] = cb[gid];
    } else if (bid < (KK * DD) / 256 + 32) {
        // e2 with XLA row-reduction emulation: lane-strided seq FMA + shfl tree
        int lane = threadIdx.x & 31;
        int warp = threadIdx.x >> 5;
        int row = (bid - (KK * DD) / 256) * 8 + warp;
        const float* c = cb + (size_t)row * DD;
        float s = 0.f;
#pragma unroll
        for (int j = 0; j < DD / 32; ++j) {
            float v = c[lane + 32 * j];
            s = fmaf(v, v, s);
        }
#pragma unroll
        for (int off = 16; off; off >>= 1) s += __shfl_down_sync(FULL, s, off);
        if (lane == 0) g_e2f[row] = s;
    } else {
        if (threadIdx.x == 0) g_nflag = 0;
    }
}

// ---- main: distance GEMM (screening) + argmin + near-tie candidate capture ----
__global__ __launch_bounds__(256, 2) void vq_main(const float* __restrict__ z) {
    __shared__ float cs[DC][KK];     // 16 KB codebook chunk (k-major)
    __shared__ float xs[DC][TT];     // 4 KB  x chunk
    __shared__ float es[KK];         // 1 KB  e2
    __shared__ float redv[TT][16];   // argmin reduction values
    __shared__ int   redk[TT][16];   // argmin reduction indices
    __shared__ float bestv_s[TT];
    __shared__ int   bestk_s[TT];
    __shared__ int   cand_cnt[TT];
    __shared__ int   cand_list[TT][7];

    const int tid = threadIdx.x;
    const int tx  = tid & 15;        // k-group selector
    const int ty  = tid >> 4;        // t-group selector (0..15)
    const int t0  = ty << 2;         // 4 t's per thread
    const int b   = blockIdx.y;
    const int tg  = blockIdx.x * TT; // global t offset

    es[tid] = g_e2f[tid];

    const float* zb = z + (size_t)b * DD * TTOT + tg;  // z[b][d][tg+t]

    unsigned long long acc[4][4][2]; // [t][jj][pair]; k = tx*4 + jj*64 + 2p + half
#pragma unroll
    for (int i = 0; i < 4; ++i)
#pragma unroll
        for (int j = 0; j < 4; ++j) { acc[i][j][0] = 0ULL; acc[i][j][1] = 0ULL; }

    const int xr = tid >> 4;  // xs row this thread stages
    const int xc = tid & 15;  // xs float4 column

    for (int ch = 0; ch < NCH; ++ch) {
        const int d0 = ch * DC;
        __syncthreads();
        const float4* csrc = (const float4*)(g_ct + d0 * KK);
        float4* cdst = (float4*)cs;
#pragma unroll
        for (int j = 0; j < 4; ++j) cdst[tid + 256 * j] = csrc[tid + 256 * j];
        ((float4*)xs)[tid] = *(const float4*)(zb + (size_t)(d0 + xr) * TTOT + (xc << 2));
        __syncthreads();

#pragma unroll
        for (int dc = 0; dc < DC; ++dc) {
            const float4 xv = *(const float4*)&xs[dc][t0];
            unsigned long long xp0 = pack2(xv.x), xp1 = pack2(xv.y),
                               xp2 = pack2(xv.z), xp3 = pack2(xv.w);
#pragma unroll
            for (int jj = 0; jj < 4; ++jj) {
                const ulonglong2 cp =
                    *(const ulonglong2*)&cs[dc][(tx << 2) + (jj << 6)];
                ffma2(acc[0][jj][0], xp0, cp.x); ffma2(acc[0][jj][1], xp0, cp.y);
                ffma2(acc[1][jj][0], xp1, cp.x); ffma2(acc[1][jj][1], xp1, cp.y);
                ffma2(acc[2][jj][0], xp2, cp.x); ffma2(acc[2][jj][1], xp2, cp.y);
                ffma2(acc[3][jj][0], xp3, cp.x); ffma2(acc[3][jj][1], xp3, cp.y);
            }
        }
    }

    // per-thread argmin over its 16 k's (screening score: e2 - 2*dot)
#pragma unroll
    for (int i = 0; i < 4; ++i) {
        float bv = 3.4e38f; int bk = KK;
#pragma unroll
        for (int jj = 0; jj < 4; ++jj) {
#pragma unroll
            for (int p = 0; p < 2; ++p) {
                unsigned long long v = acc[i][jj][p];
                int k0 = (tx << 2) + (jj << 6) + (p << 1);
                float s0 = es[k0]     - 2.0f * lo32(v);
                float s1 = es[k0 + 1] - 2.0f * hi32(v);
                if (s0 < bv || (s0 == bv && k0 < bk))       { bv = s0; bk = k0; }
                if (s1 < bv || (s1 == bv && (k0 + 1) < bk)) { bv = s1; bk = k0 + 1; }
            }
        }
        redv[t0 + i][tx] = bv;
        redk[t0 + i][tx] = bk;
    }
    __syncthreads();

    if (tid < TT) {
        float bv = redv[tid][0]; int bk = redk[tid][0];
#pragma unroll
        for (int j = 1; j < 16; ++j) {
            float v = redv[tid][j]; int k = redk[tid][j];
            if (v < bv || (v == bv && k < bk)) { bv = v; bk = k; }
        }
        bestv_s[tid] = bv;
        bestk_s[tid] = bk;
        cand_cnt[tid] = 0;
        g_idx[b * TTOT + tg + tid] = bk;
    }
    __syncthreads();

    // phase 2: collect near-tie candidates (score <= best + TAU, k != best)
#pragma unroll
    for (int i = 0; i < 4; ++i) {
        const int t = t0 + i;
        const float thr = bestv_s[t] + TAU;
        const int bk = bestk_s[t];
#pragma unroll
        for (int jj = 0; jj < 4; ++jj) {
#pragma unroll
            for (int p = 0; p < 2; ++p) {
                unsigned long long v = acc[i][jj][p];
                int k0 = (tx << 2) + (jj << 6) + (p << 1);
                float s0 = es[k0]     - 2.0f * lo32(v);
                float s1 = es[k0 + 1] - 2.0f * hi32(v);
                if (s0 <= thr && k0 != bk) {
                    int slot = atomicAdd(&cand_cnt[t], 1);
                    if (slot < 7) cand_list[t][slot] = k0;
                }
                if (s1 <= thr && (k0 + 1) != bk) {
                    int slot = atomicAdd(&cand_cnt[t], 1);
                    if (slot < 7) cand_list[t][slot] = k0 + 1;
                }
            }
        }
    }
    __syncthreads();

    if (tid < TT && cand_cnt[tid] > 0) {
        int slot = atomicAdd(&g_nflag, 1);
        if (slot < MAXF) {
            g_fpt[slot] = (b << 12) | (tg + tid);
            int c = cand_cnt[tid];
            if (c <= 7) {
                g_fcand[slot][0] = bestk_s[tid];
#pragma unroll
                for (int j = 0; j < 7; ++j)
                    if (j < c) g_fcand[slot][1 + j] = cand_list[tid][j];
                g_fcnt[slot] = c + 1;
            } else {
                g_fcnt[slot] = -1;  // scan all 256
            }
        }
    }
}

// ---- refine: reference-fp32-EMULATED re-decision of flagged points ----
// dot: single sequential fp32 FMA chain, d ascending (cuBLAS SIMT hypothesis)
// x2:  XLA row reduction emulation: lane-strided partials + shfl tree
// dist = fl(fl(x2 - 2*dot) + e2); argmin lowest-index on ties
__global__ void vq_refine(const float* __restrict__ z, const float* __restrict__ cb) {
    const unsigned FULL = 0xffffffffu;
    __shared__ float zsh[4][DD];
    const int lane = threadIdx.x & 31;
    const int warp = threadIdx.x >> 5;
    const int warps_total = gridDim.x * (blockDim.x >> 5);
    const int wg = blockIdx.x * (blockDim.x >> 5) + warp;

    int n = g_nflag;
    if (n > MAXF) n = MAXF;

    for (int e = wg; e < n; e += warps_total) {
        const int pt = g_fpt[e];
        const int b = pt >> 12;
        const int t = pt & 4095;
        const float* zp = z + (size_t)b * DD * TTOT + t;

        // cache the z row
        for (int d = lane; d < DD; d += 32) zsh[warp][d] = zp[(size_t)d * TTOT];
        __syncwarp();

        // x2f: XLA-style warp row reduction
        float s = 0.f;
#pragma unroll
        for (int j = 0; j < DD / 32; ++j) {
            float v = zsh[warp][lane + 32 * j];
            s = fmaf(v, v, s);
        }
#pragma unroll
        for (int off = 16; off; off >>= 1) s += __shfl_down_sync(FULL, s, off);
        const float x2f = __shfl_sync(FULL, s, 0);

        const int cnt = g_fcnt[e];
        const int ncand = (cnt < 0) ? KK : cnt;

        float bestdf = 3.4e38f; int bestk = 1 << 30;
        for (int c = lane; c < ncand; c += 32) {
            const int k = (cnt < 0) ? c : g_fcand[e][c];
            const float* ck = cb + (size_t)k * DD;
            float dot = 0.f;
#pragma unroll 8
            for (int d = 0; d < DD; ++d) dot = fmaf(zsh[warp][d], ck[d], dot);
            float df = __fadd_rn(__fsub_rn(x2f, 2.0f * dot), g_e2f[k]);
            if (df < bestdf || (df == bestdf && k < bestk)) { bestdf = df; bestk = k; }
        }
        // warp argmin reduce (value, then lowest index)
#pragma unroll
        for (int off = 16; off; off >>= 1) {
            float od = __shfl_down_sync(FULL, bestdf, off);
            int   ok = __shfl_down_sync(FULL, bestk, off);
            if (od < bestdf || (od == bestdf && ok < bestk)) { bestdf = od; bestk = ok; }
        }
        if (lane == 0) g_idx[b * TTOT + t] = bestk;
        __syncwarp();
    }
}

// ---- writer: quantize (STE arithmetic mimic) + indices + loss partials ----
__global__ __launch_bounds__(256) void vq_write(const float* __restrict__ z,
                                                float* __restrict__ out) {
    __shared__ float lred[256];
    const int tid = threadIdx.x;
    const int b = blockIdx.y;
    const int t = blockIdx.x * 256 + tid;
    const int k = g_idx[b * TTOT + t];

    out[Q_ELEMS + (size_t)b * TTOT + t] = (float)k;

    const float* zp = z + (size_t)b * DD * TTOT + t;
    float* op = out + (size_t)b * DD * TTOT + t;
    float lacc = 0.f;
#pragma unroll 4
    for (int d = 0; d < DD; ++d) {
        float x = zp[(size_t)d * TTOT];
        float q = g_ct[d * KK + k];
        op[(size_t)d * TTOT] = x + (q - x);  // STE arithmetic, matches reference
        float df = q - x;
        lacc += df * df;
    }
    lred[tid] = lacc;
    __syncthreads();
    for (int s = 128; s > 0; s >>= 1) {
        if (tid < s) lred[tid] += lred[tid + s];
        __syncthreads();
    }
    if (tid == 0) g_partials[b * gridDim.x + blockIdx.x] = lred[0];
}

// ---- finalize: deterministic loss reduction ----
__global__ void vq_finalize(float* __restrict__ out) {
    __shared__ float s[256];
    float a = 0.f;
    for (int j = threadIdx.x; j < 512; j += 256) a += g_partials[j];
    s[threadIdx.x] = a;
    __syncthreads();
    for (int st = 128; st > 0; st >>= 1) {
        if (threadIdx.x < st) s[threadIdx.x] += s[threadIdx.x + st];
        __syncthreads();
    }
    if (threadIdx.x == 0)
        out[Q_ELEMS + IDX_ELEMS] =
            0.25f * s[0] / (float)((size_t)BB * TTOT * DD);
}

extern "C" void kernel_launch(void* const* d_in, const int* in_sizes, int n_in,
                              void* d_out, int out_size) {
    const float* z  = (const float*)d_in[0];   // [B, D, T] fp32
    const float* cb = (const float*)d_in[1];   // [K, D] fp32
    float* out = (float*)d_out;

    vq_prep<<<(KK * DD) / 256 + 33, 256>>>(cb);
    dim3 grid(TTOT / TT, BB);
    vq_main<<<grid, 256>>>(z);
    vq_refine<<<64, 128>>>(z, cb);
    dim3 wgrid(TTOT / 256, BB);
    vq_write<<<wgrid, 256>>>(z, out);
    vq_finalize<<<1, 256>>>(out);
}

// round 4
// speedup vs baseline: 1.2455x; 1.2455x over previous
#include <cuda_runtime.h>

// Problem constants
#define BB   32
#define DD   384
#define TTOT 4096
#define KK   256
#define TT   64            // t-tile per block
#define DC   16            // d-chunk
#define NCH  (DD / DC)     // 24 chunks
#define TAU  1e-2f         // near-tie screening margin
#define MAXF 32768         // max flagged points
#define NPART (BB * (TTOT / TT))   // 2048 loss partials

// Output layout: quantize [B,D,T] | indices [B,T] (as float) | loss (1 float)
#define Q_ELEMS   ((size_t)BB * DD * TTOT)
#define IDX_ELEMS ((size_t)BB * TTOT)

// Scratch (no cudaMalloc allowed)
__device__ float  g_ct[DD * KK];        // transposed codebook ct[d][k]
__device__ float  g_e2f[KK];            // ||c_k||^2, XLA-emulated fp32 rounding
__device__ int    g_idx[BB * TTOT];     // chosen code per point
__device__ float  g_partials[NPART];    // per-block loss partials (sum of dists)
__device__ int    g_nflag;              // flagged-point count
__device__ int    g_fpt[MAXF];          // packed (b<<12)|t
__device__ int    g_fcnt[MAXF];         // candidate count (-1 => scan all 256)
__device__ int    g_fold[MAXF];         // screening-best index at flag time
__device__ int    g_fcand[MAXF][8];     // candidate code ids (slot 0 = screening best)
__device__ float  g_ldelta[MAXF];       // refine loss deltas (new - old dist)

// ---- packed f32x2 helpers (Blackwell FFMA2) ----
__device__ __forceinline__ unsigned long long pack2(float x) {
    unsigned long long r;
    unsigned u = __float_as_uint(x);
    asm("mov.b64 %0, {%1, %1};" : "=l"(r) : "r"(u));
    return r;
}
__device__ __forceinline__ void ffma2(unsigned long long& d,
                                      unsigned long long a,
                                      unsigned long long b) {
    asm("fma.rn.f32x2 %0, %1, %2, %0;" : "+l"(d) : "l"(a), "l"(b));
}
__device__ __forceinline__ float lo32(unsigned long long v) {
    return __uint_as_float((unsigned)(v & 0xffffffffULL));
}
__device__ __forceinline__ float hi32(unsigned long long v) {
    return __uint_as_float((unsigned)(v >> 32));
}

// ---- prep: transpose codebook + XLA-emulated e2 + reset flag counter ----
__global__ void vq_prep(const float* __restrict__ cb) {
    const unsigned FULL = 0xffffffffu;
    int bid = blockIdx.x;
    if (bid < (KK * DD) / 256) {
        int gid = bid * 256 + threadIdx.x;
        int k = gid / DD;
        int d = gid - k * DD;
        g_ct[d * KK + k] = cb[gid];
    } else if (bid < (KK * DD) / 256 + 32) {
        // e2 with XLA row-reduction emulation: lane-strided seq FMA + shfl tree
        int lane = threadIdx.x & 31;
        int warp = threadIdx.x >> 5;
        int row = (bid - (KK * DD) / 256) * 8 + warp;
        const float* c = cb + (size_t)row * DD;
        float s = 0.f;
#pragma unroll
        for (int j = 0; j < DD / 32; ++j) {
            float v = c[lane + 32 * j];
            s = fmaf(v, v, s);
        }
#pragma unroll
        for (int off = 16; off; off >>= 1) s += __shfl_down_sync(FULL, s, off);
        if (lane == 0) g_e2f[row] = s;
    } else {
        if (threadIdx.x == 0) g_nflag = 0;
    }
}

// ---- main: screening GEMM + argmin + flags + fused loss partial ----
__global__ __launch_bounds__(256, 2) void vq_main(const float* __restrict__ z) {
    __shared__ float cs[DC][KK];     // 16 KB codebook chunk (k-major)
    __shared__ float xs[DC][TT];     // 4 KB  x chunk
    __shared__ float es[KK];         // 1 KB  e2
    __shared__ float redv[TT][16];   // argmin reduction values
    __shared__ int   redk[TT][16];   // argmin reduction indices
    __shared__ float bestv_s[TT];
    __shared__ int   bestk_s[TT];
    __shared__ int   cand_cnt[TT];
    __shared__ int   cand_list[TT][7];
    __shared__ float lred[256];

    const int tid = threadIdx.x;
    const int tx  = tid & 15;        // k-group selector
    const int ty  = tid >> 4;        // t-group selector (0..15)
    const int t0  = ty << 2;         // 4 t's per thread
    const int b   = blockIdx.y;
    const int tg  = blockIdx.x * TT; // global t offset

    es[tid] = g_e2f[tid];

    const float* zb = z + (size_t)b * DD * TTOT + tg;  // z[b][d][tg+t]

    unsigned long long acc[4][4][2]; // [t][jj][pair]
#pragma unroll
    for (int i = 0; i < 4; ++i)
#pragma unroll
        for (int j = 0; j < 4; ++j) { acc[i][j][0] = 0ULL; acc[i][j][1] = 0ULL; }

    const int xr = tid >> 4;  // xs row this thread stages
    const int xc = tid & 15;  // xs float4 column
    float x2stage = 0.f;      // block-level sum-of-squares contribution

    for (int ch = 0; ch < NCH; ++ch) {
        const int d0 = ch * DC;
        __syncthreads();
        const float4* csrc = (const float4*)(g_ct + d0 * KK);
        float4* cdst = (float4*)cs;
#pragma unroll
        for (int j = 0; j < 4; ++j) cdst[tid + 256 * j] = csrc[tid + 256 * j];
        const float4 sv = *(const float4*)(zb + (size_t)(d0 + xr) * TTOT + (xc << 2));
        ((float4*)xs)[tid] = sv;
        x2stage = fmaf(sv.x, sv.x, fmaf(sv.y, sv.y,
                  fmaf(sv.z, sv.z, fmaf(sv.w, sv.w, x2stage))));
        __syncthreads();

#pragma unroll
        for (int dc = 0; dc < DC; ++dc) {
            const float4 xv = *(const float4*)&xs[dc][t0];
            unsigned long long xp0 = pack2(xv.x), xp1 = pack2(xv.y),
                               xp2 = pack2(xv.z), xp3 = pack2(xv.w);
#pragma unroll
            for (int jj = 0; jj < 4; ++jj) {
                const ulonglong2 cp =
                    *(const ulonglong2*)&cs[dc][(tx << 2) + (jj << 6)];
                ffma2(acc[0][jj][0], xp0, cp.x); ffma2(acc[0][jj][1], xp0, cp.y);
                ffma2(acc[1][jj][0], xp1, cp.x); ffma2(acc[1][jj][1], xp1, cp.y);
                ffma2(acc[2][jj][0], xp2, cp.x); ffma2(acc[2][jj][1], xp2, cp.y);
                ffma2(acc[3][jj][0], xp3, cp.x); ffma2(acc[3][jj][1], xp3, cp.y);
            }
        }
    }

    // per-thread argmin over its 16 k's (screening score: e2 - 2*dot)
#pragma unroll
    for (int i = 0; i < 4; ++i) {
        float bv = 3.4e38f; int bk = KK;
#pragma unroll
        for (int jj = 0; jj < 4; ++jj) {
#pragma unroll
            for (int p = 0; p < 2; ++p) {
                unsigned long long v = acc[i][jj][p];
                int k0 = (tx << 2) + (jj << 6) + (p << 1);
                float s0 = es[k0]     - 2.0f * lo32(v);
                float s1 = es[k0 + 1] - 2.0f * hi32(v);
                if (s0 < bv || (s0 == bv && k0 < bk))       { bv = s0; bk = k0; }
                if (s1 < bv || (s1 == bv && (k0 + 1) < bk)) { bv = s1; bk = k0 + 1; }
            }
        }
        redv[t0 + i][tx] = bv;
        redk[t0 + i][tx] = bk;
    }
    __syncthreads();

    if (tid < TT) {
        float bv = redv[tid][0]; int bk = redk[tid][0];
#pragma unroll
        for (int j = 1; j < 16; ++j) {
            float v = redv[tid][j]; int k = redk[tid][j];
            if (v < bv || (v == bv && k < bk)) { bv = v; bk = k; }
        }
        bestv_s[tid] = bv;
        bestk_s[tid] = bk;
        cand_cnt[tid] = 0;
        g_idx[b * TTOT + tg + tid] = bk;
    }
    __syncthreads();

    // fused loss partial: sum_t dist_t = (sum x2 staged) + (sum_t bestv_t)
    lred[tid] = x2stage + ((tid < TT) ? bestv_s[tid] : 0.f);

    // phase 2: collect near-tie candidates (score <= best + TAU, k != best)
#pragma unroll
    for (int i = 0; i < 4; ++i) {
        const int t = t0 + i;
        const float thr = bestv_s[t] + TAU;
        const int bk = bestk_s[t];
#pragma unroll
        for (int jj = 0; jj < 4; ++jj) {
#pragma unroll
            for (int p = 0; p < 2; ++p) {
                unsigned long long v = acc[i][jj][p];
                int k0 = (tx << 2) + (jj << 6) + (p << 1);
                float s0 = es[k0]     - 2.0f * lo32(v);
                float s1 = es[k0 + 1] - 2.0f * hi32(v);
                if (s0 <= thr && k0 != bk) {
                    int slot = atomicAdd(&cand_cnt[t], 1);
                    if (slot < 7) cand_list[t][slot] = k0;
                }
                if (s1 <= thr && (k0 + 1) != bk) {
                    int slot = atomicAdd(&cand_cnt[t], 1);
                    if (slot < 7) cand_list[t][slot] = k0 + 1;
                }
            }
        }
    }
    __syncthreads();

    if (tid < TT && cand_cnt[tid] > 0) {
        int slot = atomicAdd(&g_nflag, 1);
        if (slot < MAXF) {
            g_fpt[slot] = (b << 12) | (tg + tid);
            g_fold[slot] = bestk_s[tid];
            int c = cand_cnt[tid];
            if (c <= 7) {
                g_fcand[slot][0] = bestk_s[tid];
#pragma unroll
                for (int j = 0; j < 7; ++j)
                    if (j < c) g_fcand[slot][1 + j] = cand_list[tid][j];
                g_fcnt[slot] = c + 1;
            } else {
                g_fcnt[slot] = -1;  // scan all 256
            }
        }
    }

    // block loss reduction
    for (int s = 128; s > 0; s >>= 1) {
        if (tid < s) lred[tid] += lred[tid + s];
        __syncthreads();
    }
    if (tid == 0) g_partials[b * gridDim.x + blockIdx.x] = lred[0];
}

// ---- refine: reference-fp32-EMULATED re-decision of flagged points ----
__global__ void vq_refine(const float* __restrict__ z, const float* __restrict__ cb) {
    const unsigned FULL = 0xffffffffu;
    __shared__ float zsh[4][DD];
    const int lane = threadIdx.x & 31;
    const int warp = threadIdx.x >> 5;
    const int warps_total = gridDim.x * (blockDim.x >> 5);
    const int wg = blockIdx.x * (blockDim.x >> 5) + warp;

    int n = g_nflag;
    if (n > MAXF) n = MAXF;

    for (int e = wg; e < n; e += warps_total) {
        const int pt = g_fpt[e];
        const int b = pt >> 12;
        const int t = pt & 4095;
        const int kold = g_fold[e];
        const float* zp = z + (size_t)b * DD * TTOT + t;

        for (int d = lane; d < DD; d += 32) zsh[warp][d] = zp[(size_t)d * TTOT];
        __syncwarp();

        // x2f: XLA-style warp row reduction
        float s = 0.f;
#pragma unroll
        for (int j = 0; j < DD / 32; ++j) {
            float v = zsh[warp][lane + 32 * j];
            s = fmaf(v, v, s);
        }
#pragma unroll
        for (int off = 16; off; off >>= 1) s += __shfl_down_sync(FULL, s, off);
        const float x2f = __shfl_sync(FULL, s, 0);

        const int cnt = g_fcnt[e];
        const int ncand = (cnt < 0) ? KK : cnt;

        float bestdf = 3.4e38f; int bestk = 1 << 30;
        float dfold_l = 0.f;
        for (int c = lane; c < ncand; c += 32) {
            const int k = (cnt < 0) ? c : g_fcand[e][c];
            const float* ck = cb + (size_t)k * DD;
            float dot = 0.f;
#pragma unroll 8
            for (int d = 0; d < DD; ++d) dot = fmaf(zsh[warp][d], ck[d], dot);
            float df = __fadd_rn(__fsub_rn(x2f, 2.0f * dot), g_e2f[k]);
            if (df < bestdf || (df == bestdf && k < bestk)) { bestdf = df; bestk = k; }
            if (k == kold) dfold_l = df;
        }
        // warp argmin reduce + old-dist gather (exactly one lane nonzero)
#pragma unroll
        for (int off = 16; off; off >>= 1) {
            float od = __shfl_down_sync(FULL, bestdf, off);
            int   ok = __shfl_down_sync(FULL, bestk, off);
            float oo = __shfl_down_sync(FULL, dfold_l, off);
            if (od < bestdf || (od == bestdf && ok < bestk)) { bestdf = od; bestk = ok; }
            dfold_l += oo;
        }
        if (lane == 0) {
            g_idx[b * TTOT + t] = bestk;
            g_ldelta[e] = bestdf - dfold_l;   // 0 when decision unchanged
        }
        __syncwarp();
    }
}

// ---- writer: gather-only quantize + indices (no z read, STG.128) ----
__global__ __launch_bounds__(256) void vq_write(float* __restrict__ out) {
    const int tid = threadIdx.x;
    const int b  = blockIdx.y;
    const int dz = blockIdx.z;                       // d-group (0..3), 96 d each
    const int t4 = (blockIdx.x * 256 + tid) << 2;    // 4 consecutive t's

    const int4 kk = *(const int4*)&g_idx[b * TTOT + t4];

    if (dz == 0) {
        float4 fi = make_float4((float)kk.x, (float)kk.y, (float)kk.z, (float)kk.w);
        *(float4*)&out[Q_ELEMS + (size_t)b * TTOT + t4] = fi;
    }

    float* ob = out + (size_t)b * DD * TTOT + t4;
    const int dlo = dz * (DD / 4);
#pragma unroll 4
    for (int d = dlo; d < dlo + DD / 4; ++d) {
        const float* row = g_ct + d * KK;
        float4 q = make_float4(row[kk.x], row[kk.y], row[kk.z], row[kk.w]);
        *(float4*)&ob[(size_t)d * TTOT] = q;
    }
}

// ---- finalize: deterministic loss reduction (partials + refine deltas) ----
__global__ void vq_finalize(float* __restrict__ out) {
    __shared__ float s[256];
    int n = g_nflag;
    if (n > MAXF) n = MAXF;
    float a = 0.f;
    for (int j = threadIdx.x; j < NPART; j += 256) a += g_partials[j];
    for (int e = threadIdx.x; e < n; e += 256) a += g_ldelta[e];
    s[threadIdx.x] = a;
    __syncthreads();
    for (int st = 128; st > 0; st >>= 1) {
        if (threadIdx.x < st) s[threadIdx.x] += s[threadIdx.x + st];
        __syncthreads();
    }
    if (threadIdx.x == 0)
        out[Q_ELEMS + IDX_ELEMS] =
            0.25f * s[0] / (float)((size_t)BB * TTOT * DD);
}

extern "C" void kernel_launch(void* const* d_in, const int* in_sizes, int n_in,
                              void* d_out, int out_size) {
    const float* z  = (const float*)d_in[0];   // [B, D, T] fp32
    const float* cb = (const float*)d_in[1];   // [K, D] fp32
    float* out = (float*)d_out;

    vq_prep<<<(KK * DD) / 256 + 33, 256>>>(cb);
    dim3 grid(TTOT / TT, BB);
    vq_main<<<grid, 256>>>(z);
    vq_refine<<<64, 128>>>(z, cb);
    dim3 wgrid(TTOT / 1024, BB, 4);
    vq_write<<<wgrid, 256>>>(out);
    vq_finalize<<<1, 256>>>(out);
}

// round 6
// speedup vs baseline: 1.7867x; 1.4345x over previous
#include <cuda_runtime.h>
#include <cuda_bf16.h>
#include <cstdint>

// Problem constants
#define BB    32
#define DD    384
#define TTOT  4096
#define KK    256
#define TTILE 64
#define KC    64
#define NCHK  6
#define TAU   1e-2f
#define MAXF  32768
#define NPART 2048

#define Q_ELEMS   ((size_t)BB * DD * TTOT)
#define IDX_ELEMS ((size_t)BB * TTOT)

// SMEM layout (bytes)
#define A_OFF     0                  // z bf16 hi(8K)+lo(8K), rows=t, 128B, swizzled
#define B_OFF     16384              // cb bf16 hi(32K)+lo(32K), rows=k, 128B, swizzled
#define ZF_OFF    81920              // fp32 bounce [64][68]
#define ES_OFF    99328              // e2 [256] f32
#define REDV_OFF  100352             // [64][4] f32
#define REDK_OFF  101376             // [64][4] i32
#define BV_OFF    102400             // [64] f32
#define BK_OFF    102656             // [64] i32
#define CC_OFF    102912             // [64] i32
#define CL_OFF    103168             // [64][7] i32
#define LRED_OFF  104960             // [256] f32
#define SMEM_SZ   105984

// Scratch
__device__ float  g_ct[DD * KK];
__device__ float  g_e2f[KK];
__device__ int    g_idx[BB * TTOT];
__device__ float  g_partials[NPART];
__device__ int    g_nflag;
__device__ int    g_fpt[MAXF];
__device__ int    g_fcnt[MAXF];
__device__ int    g_fold[MAXF];
__device__ int    g_fcand[MAXF][8];
__device__ float  g_ldelta[MAXF];
__device__ unsigned short g_bswh[NCHK * KK * KC];  // pre-swizzled bf16 codebook hi
__device__ unsigned short g_bswl[NCHK * KK * KC];  // lo

static __device__ __forceinline__ uint32_t smem_u32(const void* p) {
    uint32_t a;
    asm("{ .reg .u64 t; cvta.to.shared.u64 t, %1; cvt.u32.u64 %0, t; }"
        : "=r"(a) : "l"(p));
    return a;
}

#define LDSM4(r, ad) \
    asm volatile("ldmatrix.sync.aligned.m8n8.x4.shared.b16 {%0,%1,%2,%3}, [%4];" \
        : "=r"((r)[0]), "=r"((r)[1]), "=r"((r)[2]), "=r"((r)[3]) : "r"(ad))

#define MMA16816(d, a, b0, b1) \
    asm volatile("mma.sync.aligned.m16n8k16.row.col.f32.bf16.bf16.f32 " \
        "{%0,%1,%2,%3},{%4,%5,%6,%7},{%8,%9},{%0,%1,%2,%3};" \
        : "+f"((d)[0]), "+f"((d)[1]), "+f"((d)[2]), "+f"((d)[3]) \
        : "r"((a)[0]), "r"((a)[1]), "r"((a)[2]), "r"((a)[3]), "r"(b0), "r"(b1))

// ---- prep: g_ct transpose + XLA-emulated e2 + bf16 split/swizzle codebook + reset ----
__global__ void vq_prep(const float* __restrict__ cb) {
    const unsigned FULL = 0xffffffffu;
    int bid = blockIdx.x;
    if (bid < 384) {
        int gid = bid * 256 + threadIdx.x;
        int k = gid / DD;
        int d = gid - k * DD;
        g_ct[d * KK + k] = cb[gid];
    } else if (bid < 416) {
        int lane = threadIdx.x & 31;
        int warp = threadIdx.x >> 5;
        int row = (bid - 384) * 8 + warp;
        const float* c = cb + (size_t)row * DD;
        float s = 0.f;
#pragma unroll
        for (int j = 0; j < DD / 32; ++j) {
            float v = c[lane + 32 * j];
            s = fmaf(v, v, s);
        }
#pragma unroll
        for (int off = 16; off; off >>= 1) s += __shfl_down_sync(FULL, s, off);
        if (lane == 0) g_e2f[row] = s;
    } else if (bid < 800) {
        int gid = (bid - 416) * 256 + threadIdx.x;   // < 98304
        int k = gid / DD;
        int d = gid - k * DD;
        float x = cb[gid];
        __nv_bfloat16 h = __float2bfloat16(x);
        __nv_bfloat16 l = __float2bfloat16(x - __bfloat162float(h));
        int c   = d >> 6;
        int din = d & 63;
        int idx16 = c * (KK * KC) + k * KC
                  + ((((unsigned)(din * 2)) ^ ((unsigned)(k & 7) * 16)) >> 1);
        g_bswh[idx16] = __bfloat16_as_ushort(h);
        g_bswl[idx16] = __bfloat16_as_ushort(l);
    } else {
        if (threadIdx.x == 0) g_nflag = 0;
    }
}

// ---- main: mma.sync bf16-split screening + argmin + flags + loss ----
__global__ __launch_bounds__(256, 1) void vq_main(const float* __restrict__ z) {
    extern __shared__ char smem[];
    const uint32_t sb = smem_u32(smem);
    const int tid  = threadIdx.x;
    const int lane = tid & 31;
    const int w    = tid >> 5;
    const int wm   = w & 1;    // t slice (32 t)
    const int wn   = w >> 1;   // code slice (64 codes)
    const int b    = blockIdx.y;
    const int tg   = blockIdx.x * TTILE;

    ((float*)(smem + ES_OFF))[tid] = g_e2f[tid];

    const float* zb = z + (size_t)b * DD * TTOT + tg;
    float* zf = (float*)(smem + ZF_OFF);

    float acc[2][8][4];   // [mi][n8 tile][frag]
#pragma unroll
    for (int i = 0; i < 2; ++i)
#pragma unroll
        for (int j = 0; j < 8; ++j)
#pragma unroll
            for (int q = 0; q < 4; ++q) acc[i][j][q] = 0.f;

    float x2acc = 0.f;

    for (int c = 0; c < NCHK; ++c) {
        __syncthreads();
        // stage codebook chunk (pre-swizzled) hi+lo: 64KB
        {
            const uint4* sh = (const uint4*)(g_bswh + c * (KK * KC));
            const uint4* sl = (const uint4*)(g_bswl + c * (KK * KC));
            uint4* dh = (uint4*)(smem + B_OFF);
            uint4* dl = (uint4*)(smem + B_OFF + 32768);
#pragma unroll
            for (int j = 0; j < 8; ++j) {
                dh[tid + 256 * j] = sh[tid + 256 * j];
                dl[tid + 256 * j] = sl[tid + 256 * j];
            }
        }
        // z chunk -> fp32 bounce (coalesced along t) + x2 accumulation
#pragma unroll
        for (int p = 0; p < 4; ++p) {
            int d  = p * 16 + (tid >> 4);
            int t4 = tid & 15;
            float4 v = *(const float4*)(zb + (size_t)(c * KC + d) * TTOT + t4 * 4);
            *(float4*)(zf + d * 68 + t4 * 4) = v;
            x2acc = fmaf(v.x, v.x, fmaf(v.y, v.y,
                     fmaf(v.z, v.z, fmaf(v.w, v.w, x2acc))));
        }
        __syncthreads();
        // repack: bounce -> A tile (rows=t, bf16 hi/lo pairs along d, swizzled)
        {
            int t  = tid & 63;
            int dg = tid >> 6;
#pragma unroll
            for (int j = 0; j < 8; ++j) {
                int d0 = dg * 16 + j * 2;
                float f0 = zf[d0 * 68 + t];
                float f1 = zf[(d0 + 1) * 68 + t];
                __nv_bfloat16 h0 = __float2bfloat16(f0), h1 = __float2bfloat16(f1);
                __nv_bfloat16 l0 = __float2bfloat16(f0 - __bfloat162float(h0));
                __nv_bfloat16 l1 = __float2bfloat16(f1 - __bfloat162float(h1));
                unsigned hw = ((unsigned)__bfloat16_as_ushort(h1) << 16) | __bfloat16_as_ushort(h0);
                unsigned lw = ((unsigned)__bfloat16_as_ushort(l1) << 16) | __bfloat16_as_ushort(l0);
                unsigned off = (unsigned)t * 128 + (((unsigned)(d0 * 2)) ^ ((unsigned)(t & 7) * 16));
                *(unsigned*)(smem + A_OFF + off) = hw;
                *(unsigned*)(smem + A_OFF + 8192 + off) = lw;
            }
        }
        __syncthreads();

        // MMA: 4 k16 steps over this 64-d chunk, 3-term split
#pragma unroll
        for (int ks = 0; ks < 4; ++ks) {
            uint32_t ah[2][4], al[2][4];
#pragma unroll
            for (int mi = 0; mi < 2; ++mi) {
                int row = wm * 32 + mi * 16 + ((lane >> 3) & 1) * 8 + (lane & 7);
                unsigned kb = (unsigned)ks * 32 + ((lane >> 4) & 1) * 16;
                uint32_t ad = sb + A_OFF + (unsigned)row * 128 + (kb ^ ((unsigned)(row & 7) * 16));
                LDSM4(ah[mi], ad);
                LDSM4(al[mi], ad + 8192);
            }
#pragma unroll
            for (int ng = 0; ng < 4; ++ng) {
                int n = wn * 64 + ng * 16 + ((lane >> 4) & 1) * 8 + (lane & 7);
                unsigned kb = (unsigned)ks * 32 + ((lane >> 3) & 1) * 16;
                uint32_t bd = sb + B_OFF + (unsigned)n * 128 + (kb ^ ((unsigned)(n & 7) * 16));
                uint32_t bh[4], bl[4];
                LDSM4(bh, bd);
                LDSM4(bl, bd + 32768);
#pragma unroll
                for (int mi = 0; mi < 2; ++mi) {
#pragma unroll
                    for (int tile = 0; tile < 2; ++tile) {
                        float* dst = acc[mi][ng * 2 + tile];
                        MMA16816(dst, ah[mi], bh[tile * 2], bh[tile * 2 + 1]);
                        MMA16816(dst, al[mi], bh[tile * 2], bh[tile * 2 + 1]);
                        MMA16816(dst, ah[mi], bl[tile * 2], bl[tile * 2 + 1]);
                    }
                }
            }
        }
    }

    // ---- epilogue: argmin over 256 codes ----
    const float* es = (const float*)(smem + ES_OFF);
    float* redv = (float*)(smem + REDV_OFF);
    int*   redk = (int*)(smem + REDK_OFF);
    float* bestv_s = (float*)(smem + BV_OFF);
    int*   bestk_s = (int*)(smem + BK_OFF);
    int*   ccnt = (int*)(smem + CC_OFF);
    int*   clst = (int*)(smem + CL_OFF);
    float* lred = (float*)(smem + LRED_OFF);

    // thread-local best per t-row j: j = mi*2 + (frag>>1)
    float bv[4];
    int   bk[4];
#pragma unroll
    for (int j = 0; j < 4; ++j) { bv[j] = 3.4e38f; bk[j] = KK; }
#pragma unroll
    for (int mi = 0; mi < 2; ++mi)
#pragma unroll
        for (int nt = 0; nt < 8; ++nt)
#pragma unroll
            for (int ci = 0; ci < 4; ++ci) {
                int code = wn * 64 + nt * 8 + (lane & 3) * 2 + (ci & 1);
                int j = mi * 2 + (ci >> 1);
                float sc = es[code] - 2.0f * acc[mi][nt][ci];
                if (sc < bv[j] || (sc == bv[j] && code < bk[j])) { bv[j] = sc; bk[j] = code; }
            }
    const unsigned FULL = 0xffffffffu;
#pragma unroll
    for (int j = 0; j < 4; ++j) {
#pragma unroll
        for (int off = 1; off < 4; off <<= 1) {
            float ov = __shfl_xor_sync(FULL, bv[j], off);
            int   ok = __shfl_xor_sync(FULL, bk[j], off);
            if (ov < bv[j] || (ov == bv[j] && ok < bk[j])) { bv[j] = ov; bk[j] = ok; }
        }
    }
    if ((lane & 3) == 0) {
#pragma unroll
        for (int j = 0; j < 4; ++j) {
            int t = wm * 32 + (j >> 1) * 16 + (lane >> 2) + (j & 1) * 8;
            redv[t * 4 + wn] = bv[j];
            redk[t * 4 + wn] = bk[j];
        }
    }
    __syncthreads();
    if (tid < TTILE) {
        float fv = redv[tid * 4];
        int   fk = redk[tid * 4];
#pragma unroll
        for (int q = 1; q < 4; ++q) {
            float v = redv[tid * 4 + q];
            int   k = redk[tid * 4 + q];
            if (v < fv || (v == fv && k < fk)) { fv = v; fk = k; }
        }
        bestv_s[tid] = fv;
        bestk_s[tid] = fk;
        ccnt[tid] = 0;
        g_idx[b * TTOT + tg + tid] = fk;
    }
    __syncthreads();

    // candidate scan (score <= best + TAU, code != best)
#pragma unroll
    for (int mi = 0; mi < 2; ++mi)
#pragma unroll
        for (int nt = 0; nt < 8; ++nt)
#pragma unroll
            for (int ci = 0; ci < 4; ++ci) {
                int code = wn * 64 + nt * 8 + (lane & 3) * 2 + (ci & 1);
                int t = wm * 32 + mi * 16 + (lane >> 2) + ((ci >> 1) ? 8 : 0);
                float sc = es[code] - 2.0f * acc[mi][nt][ci];
                if (sc <= bestv_s[t] + TAU && code != bestk_s[t]) {
                    int slot = atomicAdd(&ccnt[t], 1);
                    if (slot < 7) clst[t * 7 + slot] = code;
                }
            }
    __syncthreads();

    if (tid < TTILE && ccnt[tid] > 0) {
        int slot = atomicAdd(&g_nflag, 1);
        if (slot < MAXF) {
            g_fpt[slot] = (b << 12) | (tg + tid);
            g_fold[slot] = bestk_s[tid];
            int cnum = ccnt[tid];
            if (cnum <= 7) {
                g_fcand[slot][0] = bestk_s[tid];
#pragma unroll
                for (int j = 0; j < 7; ++j)
                    if (j < cnum) g_fcand[slot][1 + j] = clst[tid * 7 + j];
                g_fcnt[slot] = cnum + 1;
            } else {
                g_fcnt[slot] = -1;   // scan all 256
            }
        }
    }

    // loss partial: sum x2 + sum best scores
    lred[tid] = x2acc + ((tid < TTILE) ? bestv_s[tid] : 0.f);
    __syncthreads();
    for (int s = 128; s > 0; s >>= 1) {
        if (tid < s) lred[tid] += lred[tid + s];
        __syncthreads();
    }
    if (tid == 0) g_partials[b * gridDim.x + blockIdx.x] = lred[0];
}

// ---- refine: reference-fp32-EMULATED re-decision of flagged points ----
__global__ void vq_refine(const float* __restrict__ z, const float* __restrict__ cb) {
    const unsigned FULL = 0xffffffffu;
    __shared__ float zsh[4][DD];
    const int lane = threadIdx.x & 31;
    const int warp = threadIdx.x >> 5;
    const int warps_total = gridDim.x * (blockDim.x >> 5);
    const int wg = blockIdx.x * (blockDim.x >> 5) + warp;

    int n = g_nflag;
    if (n > MAXF) n = MAXF;

    for (int e = wg; e < n; e += warps_total) {
        const int pt = g_fpt[e];
        const int b = pt >> 12;
        const int t = pt & 4095;
        const int kold = g_fold[e];
        const float* zp = z + (size_t)b * DD * TTOT + t;

        for (int d = lane; d < DD; d += 32) zsh[warp][d] = zp[(size_t)d * TTOT];
        __syncwarp();

        float s = 0.f;
#pragma unroll
        for (int j = 0; j < DD / 32; ++j) {
            float v = zsh[warp][lane + 32 * j];
            s = fmaf(v, v, s);
        }
#pragma unroll
        for (int off = 16; off; off >>= 1) s += __shfl_down_sync(FULL, s, off);
        const float x2f = __shfl_sync(FULL, s, 0);

        const int cnt = g_fcnt[e];
        const int ncand = (cnt < 0) ? KK : cnt;

        float bestdf = 3.4e38f;
        int bestk = 1 << 30;
        float dfold_l = 0.f;
        for (int c = lane; c < ncand; c += 32) {
            const int k = (cnt < 0) ? c : g_fcand[e][c];
            const float* ck = cb + (size_t)k * DD;
            float dot = 0.f;
#pragma unroll 8
            for (int d = 0; d < DD; ++d) dot = fmaf(zsh[warp][d], ck[d], dot);
            float df = __fadd_rn(__fsub_rn(x2f, 2.0f * dot), g_e2f[k]);
            if (df < bestdf || (df == bestdf && k < bestk)) { bestdf = df; bestk = k; }
            if (k == kold) dfold_l = df;
        }
#pragma unroll
        for (int off = 16; off; off >>= 1) {
            float od = __shfl_down_sync(FULL, bestdf, off);
            int   ok = __shfl_down_sync(FULL, bestk, off);
            float oo = __shfl_down_sync(FULL, dfold_l, off);
            if (od < bestdf || (od == bestdf && ok < bestk)) { bestdf = od; bestk = ok; }
            dfold_l += oo;
        }
        if (lane == 0) {
            g_idx[b * TTOT + t] = bestk;
            g_ldelta[e] = bestdf - dfold_l;
        }
        __syncwarp();
    }
}

// ---- writer: gather-only quantize + indices ----
__global__ __launch_bounds__(256) void vq_write(float* __restrict__ out) {
    const int tid = threadIdx.x;
    const int b  = blockIdx.y;
    const int dz = blockIdx.z;
    const int t4 = (blockIdx.x * 256 + tid) << 2;

    const int4 kk = *(const int4*)&g_idx[b * TTOT + t4];

    if (dz == 0) {
        float4 fi = make_float4((float)kk.x, (float)kk.y, (float)kk.z, (float)kk.w);
        *(float4*)&out[Q_ELEMS + (size_t)b * TTOT + t4] = fi;
    }

    float* ob = out + (size_t)b * DD * TTOT + t4;
    const int dlo = dz * (DD / 4);
#pragma unroll 4
    for (int d = dlo; d < dlo + DD / 4; ++d) {
        const float* row = g_ct + d * KK;
        float4 q = make_float4(row[kk.x], row[kk.y], row[kk.z], row[kk.w]);
        *(float4*)&ob[(size_t)d * TTOT] = q;
    }
}

// ---- finalize ----
__global__ void vq_finalize(float* __restrict__ out) {
    __shared__ float s[256];
    int n = g_nflag;
    if (n > MAXF) n = MAXF;
    float a = 0.f;
    for (int j = threadIdx.x; j < NPART; j += 256) a += g_partials[j];
    for (int e = threadIdx.x; e < n; e += 256) a += g_ldelta[e];
    s[threadIdx.x] = a;
    __syncthreads();
    for (int st = 128; st > 0; st >>= 1) {
        if (threadIdx.x < st) s[threadIdx.x] += s[threadIdx.x + st];
        __syncthreads();
    }
    if (threadIdx.x == 0)
        out[Q_ELEMS + IDX_ELEMS] =
            0.25f * s[0] / (float)((size_t)BB * TTOT * DD);
}

extern "C" void kernel_launch(void* const* d_in, const int* in_sizes, int n_in,
                              void* d_out, int out_size) {
    const float* z  = (const float*)d_in[0];
    const float* cb = (const float*)d_in[1];
    float* out = (float*)d_out;

    cudaFuncSetAttribute(vq_main, cudaFuncAttributeMaxDynamicSharedMemorySize, SMEM_SZ);

    vq_prep<<<801, 256>>>(cb);
    dim3 grid(TTOT / TTILE, BB);
    vq_main<<<grid, 256, SMEM_SZ>>>(z);
    vq_refine<<<64, 128>>>(z, cb);
    dim3 wgrid(TTOT / 1024, BB, 4);
    vq_write<<<wgrid, 256>>>(out);
    vq_finalize<<<1, 256>>>(out);
}

// round 7
// speedup vs baseline: 2.5837x; 1.4461x over previous
#include <cuda_runtime.h>
#include <cuda_bf16.h>
#include <cstdint>

// Problem constants
#define BB    32
#define DD    384
#define TTOT  4096
#define KK    256
#define TTILE 64
#define KC    64
#define NCHK  6
#define TAU   1e-2f
#define MAXF  32768
#define NPART 2048

#define Q_ELEMS   ((size_t)BB * DD * TTOT)
#define IDX_ELEMS ((size_t)BB * TTOT)

// SMEM layout (bytes)
#define A_OFF     0                  // z bf16 hi(8K)+lo(8K), rows=t, 128B, swizzled
#define B_OFF     16384              // cb bf16 hi(32K)+lo(32K), rows=k, 128B, swizzled
#define ZF_OFF    81920              // fp32 bounce [64][68]
#define ES_OFF    99328              // e2 [256] f32
#define REDV_OFF  100352             // [64][4] f32
#define REDK_OFF  101376             // [64][4] i32
#define BV_OFF    102400             // [64] f32
#define BK_OFF    102656             // [64] i32
#define CC_OFF    102912             // [64] i32
#define CL_OFF    103168             // [64][7] i32
#define LRED_OFF  104960             // [256] f32
#define SMEM_SZ   105984             // <= 113.6KB -> 2 CTAs/SM

// Scratch
__device__ float  g_ct[DD * KK];
__device__ float  g_e2f[KK];
__device__ int    g_idx[BB * TTOT];
__device__ float  g_partials[NPART];
__device__ int    g_nflag;
__device__ int    g_fpt[MAXF];
__device__ int    g_fcnt[MAXF];
__device__ int    g_fold[MAXF];
__device__ int    g_fcand[MAXF][8];
__device__ float  g_ldelta[MAXF];
__device__ unsigned short g_bswh[NCHK * KK * KC];  // pre-swizzled bf16 codebook hi
__device__ unsigned short g_bswl[NCHK * KK * KC];  // lo

static __device__ __forceinline__ uint32_t smem_u32(const void* p) {
    uint32_t a;
    asm("{ .reg .u64 t; cvta.to.shared.u64 t, %1; cvt.u32.u64 %0, t; }"
        : "=r"(a) : "l"(p));
    return a;
}

#define CPASYNC16(dst, src) \
    asm volatile("cp.async.cg.shared.global [%0], [%1], 16;" \
        :: "r"(dst), "l"(src) : "memory")
#define CPCOMMIT  asm volatile("cp.async.commit_group;" ::: "memory")
#define CPWAIT0   asm volatile("cp.async.wait_group 0;" ::: "memory")

#define LDSM4(r, ad) \
    asm volatile("ldmatrix.sync.aligned.m8n8.x4.shared.b16 {%0,%1,%2,%3}, [%4];" \
        : "=r"((r)[0]), "=r"((r)[1]), "=r"((r)[2]), "=r"((r)[3]) : "r"(ad))

#define MMA16816(d, a, b0, b1) \
    asm volatile("mma.sync.aligned.m16n8k16.row.col.f32.bf16.bf16.f32 " \
        "{%0,%1,%2,%3},{%4,%5,%6,%7},{%8,%9},{%0,%1,%2,%3};" \
        : "+f"((d)[0]), "+f"((d)[1]), "+f"((d)[2]), "+f"((d)[3]) \
        : "r"((a)[0]), "r"((a)[1]), "r"((a)[2]), "r"((a)[3]), "r"(b0), "r"(b1))

// ---- prep: g_ct transpose + XLA-emulated e2 + bf16 split/swizzle codebook + reset ----
__global__ void vq_prep(const float* __restrict__ cb) {
    const unsigned FULL = 0xffffffffu;
    int bid = blockIdx.x;
    if (bid < 384) {
        int gid = bid * 256 + threadIdx.x;
        int k = gid / DD;
        int d = gid - k * DD;
        g_ct[d * KK + k] = cb[gid];
    } else if (bid < 416) {
        int lane = threadIdx.x & 31;
        int warp = threadIdx.x >> 5;
        int row = (bid - 384) * 8 + warp;
        const float* c = cb + (size_t)row * DD;
        float s = 0.f;
#pragma unroll
        for (int j = 0; j < DD / 32; ++j) {
            float v = c[lane + 32 * j];
            s = fmaf(v, v, s);
        }
#pragma unroll
        for (int off = 16; off; off >>= 1) s += __shfl_down_sync(FULL, s, off);
        if (lane == 0) g_e2f[row] = s;
    } else if (bid < 800) {
        int gid = (bid - 416) * 256 + threadIdx.x;   // < 98304
        int k = gid / DD;
        int d = gid - k * DD;
        float x = cb[gid];
        __nv_bfloat16 h = __float2bfloat16(x);
        __nv_bfloat16 l = __float2bfloat16(x - __bfloat162float(h));
        int c   = d >> 6;
        int din = d & 63;
        int idx16 = c * (KK * KC) + k * KC
                  + ((((unsigned)(din * 2)) ^ ((unsigned)(k & 7) * 16)) >> 1);
        g_bswh[idx16] = __bfloat16_as_ushort(h);
        g_bswl[idx16] = __bfloat16_as_ushort(l);
    } else {
        if (threadIdx.x == 0) g_nflag = 0;
    }
}

// ---- main: mma.sync bf16-split screening + argmin + flags + loss ----
__global__ __launch_bounds__(256, 2) void vq_main(const float* __restrict__ z) {
    extern __shared__ char smem[];
    const uint32_t sb = smem_u32(smem);
    const int tid  = threadIdx.x;
    const int lane = tid & 31;
    const int w    = tid >> 5;
    const int wm   = w & 1;    // t slice (32 t)
    const int wn   = w >> 1;   // code slice (64 codes)
    const int b    = blockIdx.y;
    const int tg   = blockIdx.x * TTILE;

    ((float*)(smem + ES_OFF))[tid] = g_e2f[tid];

    const float* zb = z + (size_t)b * DD * TTOT + tg;
    float* zf = (float*)(smem + ZF_OFF);

    float acc[2][8][4];   // [mi][n8 tile][frag]
#pragma unroll
    for (int i = 0; i < 2; ++i)
#pragma unroll
        for (int j = 0; j < 8; ++j)
#pragma unroll
            for (int q = 0; q < 4; ++q) acc[i][j][q] = 0.f;

    float x2acc = 0.f;

    for (int c = 0; c < NCHK; ++c) {
        __syncthreads();   // prev MMA done reading A/B; buffers free
        // stage codebook chunk (pre-swizzled) hi+lo via cp.async: 64KB
        {
            const char* sh = (const char*)(g_bswh + c * (KK * KC));
            const char* sl = (const char*)(g_bswl + c * (KK * KC));
            uint32_t dh = sb + B_OFF + (unsigned)tid * 16;
            uint32_t dl = sb + B_OFF + 32768 + (unsigned)tid * 16;
#pragma unroll
            for (int j = 0; j < 8; ++j) {
                CPASYNC16(dh + 4096u * j, sh + (tid + 256 * j) * 16);
                CPASYNC16(dl + 4096u * j, sl + (tid + 256 * j) * 16);
            }
        }
        // z chunk -> fp32 bounce via cp.async (coalesced along t)
#pragma unroll
        for (int p = 0; p < 4; ++p) {
            int d  = p * 16 + (tid >> 4);
            int t4 = tid & 15;
            CPASYNC16(sb + ZF_OFF + (unsigned)(d * 68 + t4 * 4) * 4,
                      zb + (size_t)(c * KC + d) * TTOT + t4 * 4);
        }
        CPCOMMIT;
        CPWAIT0;
        __syncthreads();
        // repack: bounce -> A tile (rows=t, bf16 hi/lo pairs along d, swizzled) + x2
        {
            int t  = tid & 63;
            int dg = tid >> 6;
#pragma unroll
            for (int j = 0; j < 8; ++j) {
                int d0 = dg * 16 + j * 2;
                float f0 = zf[d0 * 68 + t];
                float f1 = zf[(d0 + 1) * 68 + t];
                x2acc = fmaf(f0, f0, fmaf(f1, f1, x2acc));
                __nv_bfloat16 h0 = __float2bfloat16(f0), h1 = __float2bfloat16(f1);
                __nv_bfloat16 l0 = __float2bfloat16(f0 - __bfloat162float(h0));
                __nv_bfloat16 l1 = __float2bfloat16(f1 - __bfloat162float(h1));
                unsigned hw = ((unsigned)__bfloat16_as_ushort(h1) << 16) | __bfloat16_as_ushort(h0);
                unsigned lw = ((unsigned)__bfloat16_as_ushort(l1) << 16) | __bfloat16_as_ushort(l0);
                unsigned off = (unsigned)t * 128 + (((unsigned)(d0 * 2)) ^ ((unsigned)(t & 7) * 16));
                *(unsigned*)(smem + A_OFF + off) = hw;
                *(unsigned*)(smem + A_OFF + 8192 + off) = lw;
            }
        }
        __syncthreads();

        // MMA: 4 k16 steps over this 64-d chunk, 3-term split
#pragma unroll
        for (int ks = 0; ks < 4; ++ks) {
            uint32_t ah[2][4], al[2][4];
#pragma unroll
            for (int mi = 0; mi < 2; ++mi) {
                int row = wm * 32 + mi * 16 + ((lane >> 3) & 1) * 8 + (lane & 7);
                unsigned kb = (unsigned)ks * 32 + ((lane >> 4) & 1) * 16;
                uint32_t ad = sb + A_OFF + (unsigned)row * 128 + (kb ^ ((unsigned)(row & 7) * 16));
                LDSM4(ah[mi], ad);
                LDSM4(al[mi], ad + 8192);
            }
#pragma unroll
            for (int ng = 0; ng < 4; ++ng) {
                int n = wn * 64 + ng * 16 + ((lane >> 4) & 1) * 8 + (lane & 7);
                unsigned kb = (unsigned)ks * 32 + ((lane >> 3) & 1) * 16;
                uint32_t bd = sb + B_OFF + (unsigned)n * 128 + (kb ^ ((unsigned)(n & 7) * 16));
                uint32_t bh[4], bl[4];
                LDSM4(bh, bd);
                LDSM4(bl, bd + 32768);
#pragma unroll
                for (int mi = 0; mi < 2; ++mi) {
#pragma unroll
                    for (int tile = 0; tile < 2; ++tile) {
                        float* dst = acc[mi][ng * 2 + tile];
                        MMA16816(dst, ah[mi], bh[tile * 2], bh[tile * 2 + 1]);
                        MMA16816(dst, al[mi], bh[tile * 2], bh[tile * 2 + 1]);
                        MMA16816(dst, ah[mi], bl[tile * 2], bl[tile * 2 + 1]);
                    }
                }
            }
        }
    }

    // ---- epilogue: argmin over 256 codes ----
    const float* es = (const float*)(smem + ES_OFF);
    float* redv = (float*)(smem + REDV_OFF);
    int*   redk = (int*)(smem + REDK_OFF);
    float* bestv_s = (float*)(smem + BV_OFF);
    int*   bestk_s = (int*)(smem + BK_OFF);
    int*   ccnt = (int*)(smem + CC_OFF);
    int*   clst = (int*)(smem + CL_OFF);
    float* lred = (float*)(smem + LRED_OFF);

    // thread-local best per t-row j: j = mi*2 + (frag>>1)
    float bv[4];
    int   bk[4];
#pragma unroll
    for (int j = 0; j < 4; ++j) { bv[j] = 3.4e38f; bk[j] = KK; }
#pragma unroll
    for (int mi = 0; mi < 2; ++mi)
#pragma unroll
        for (int nt = 0; nt < 8; ++nt)
#pragma unroll
            for (int ci = 0; ci < 4; ++ci) {
                int code = wn * 64 + nt * 8 + (lane & 3) * 2 + (ci & 1);
                int j = mi * 2 + (ci >> 1);
                float sc = es[code] - 2.0f * acc[mi][nt][ci];
                if (sc < bv[j] || (sc == bv[j] && code < bk[j])) { bv[j] = sc; bk[j] = code; }
            }
    const unsigned FULL = 0xffffffffu;
#pragma unroll
    for (int j = 0; j < 4; ++j) {
#pragma unroll
        for (int off = 1; off < 4; off <<= 1) {
            float ov = __shfl_xor_sync(FULL, bv[j], off);
            int   ok = __shfl_xor_sync(FULL, bk[j], off);
            if (ov < bv[j] || (ov == bv[j] && ok < bk[j])) { bv[j] = ov; bk[j] = ok; }
        }
    }
    if ((lane & 3) == 0) {
#pragma unroll
        for (int j = 0; j < 4; ++j) {
            int t = wm * 32 + (j >> 1) * 16 + (lane >> 2) + (j & 1) * 8;
            redv[t * 4 + wn] = bv[j];
            redk[t * 4 + wn] = bk[j];
        }
    }
    __syncthreads();
    if (tid < TTILE) {
        float fv = redv[tid * 4];
        int   fk = redk[tid * 4];
#pragma unroll
        for (int q = 1; q < 4; ++q) {
            float v = redv[tid * 4 + q];
            int   k = redk[tid * 4 + q];
            if (v < fv || (v == fv && k < fk)) { fv = v; fk = k; }
        }
        bestv_s[tid] = fv;
        bestk_s[tid] = fk;
        ccnt[tid] = 0;
        g_idx[b * TTOT + tg + tid] = fk;
    }
    __syncthreads();

    // candidate scan (score <= best + TAU, code != best)
#pragma unroll
    for (int mi = 0; mi < 2; ++mi)
#pragma unroll
        for (int nt = 0; nt < 8; ++nt)
#pragma unroll
            for (int ci = 0; ci < 4; ++ci) {
                int code = wn * 64 + nt * 8 + (lane & 3) * 2 + (ci & 1);
                int t = wm * 32 + mi * 16 + (lane >> 2) + ((ci >> 1) ? 8 : 0);
                float sc = es[code] - 2.0f * acc[mi][nt][ci];
                if (sc <= bestv_s[t] + TAU && code != bestk_s[t]) {
                    int slot = atomicAdd(&ccnt[t], 1);
                    if (slot < 7) clst[t * 7 + slot] = code;
                }
            }
    __syncthreads();

    if (tid < TTILE && ccnt[tid] > 0) {
        int slot = atomicAdd(&g_nflag, 1);
        if (slot < MAXF) {
            g_fpt[slot] = (b << 12) | (tg + tid);
            g_fold[slot] = bestk_s[tid];
            int cnum = ccnt[tid];
            if (cnum <= 7) {
                g_fcand[slot][0] = bestk_s[tid];
#pragma unroll
                for (int j = 0; j < 7; ++j)
                    if (j < cnum) g_fcand[slot][1 + j] = clst[tid * 7 + j];
                g_fcnt[slot] = cnum + 1;
            } else {
                g_fcnt[slot] = -1;   // scan all 256
            }
        }
    }

    // loss partial: sum x2 + sum best scores
    lred[tid] = x2acc + ((tid < TTILE) ? bestv_s[tid] : 0.f);
    __syncthreads();
    for (int s = 128; s > 0; s >>= 1) {
        if (tid < s) lred[tid] += lred[tid + s];
        __syncthreads();
    }
    if (tid == 0) g_partials[b * gridDim.x + blockIdx.x] = lred[0];
}

// ---- refine: reference-fp32-EMULATED re-decision of flagged points ----
__global__ void vq_refine(const float* __restrict__ z, const float* __restrict__ cb) {
    const unsigned FULL = 0xffffffffu;
    __shared__ float zsh[4][DD];
    const int lane = threadIdx.x & 31;
    const int warp = threadIdx.x >> 5;
    const int warps_total = gridDim.x * (blockDim.x >> 5);
    const int wg = blockIdx.x * (blockDim.x >> 5) + warp;

    int n = g_nflag;
    if (n > MAXF) n = MAXF;

    for (int e = wg; e < n; e += warps_total) {
        const int pt = g_fpt[e];
        const int b = pt >> 12;
        const int t = pt & 4095;
        const int kold = g_fold[e];
        const float* zp = z + (size_t)b * DD * TTOT + t;

        for (int d = lane; d < DD; d += 32) zsh[warp][d] = zp[(size_t)d * TTOT];
        __syncwarp();

        float s = 0.f;
#pragma unroll
        for (int j = 0; j < DD / 32; ++j) {
            float v = zsh[warp][lane + 32 * j];
            s = fmaf(v, v, s);
        }
#pragma unroll
        for (int off = 16; off; off >>= 1) s += __shfl_down_sync(FULL, s, off);
        const float x2f = __shfl_sync(FULL, s, 0);

        const int cnt = g_fcnt[e];
        const int ncand = (cnt < 0) ? KK : cnt;

        float bestdf = 3.4e38f;
        int bestk = 1 << 30;
        float dfold_l = 0.f;
        for (int c = lane; c < ncand; c += 32) {
            const int k = (cnt < 0) ? c : g_fcand[e][c];
            const float* ck = cb + (size_t)k * DD;
            float dot = 0.f;
#pragma unroll 8
            for (int d = 0; d < DD; ++d) dot = fmaf(zsh[warp][d], ck[d], dot);
            float df = __fadd_rn(__fsub_rn(x2f, 2.0f * dot), g_e2f[k]);
            if (df < bestdf || (df == bestdf && k < bestk)) { bestdf = df; bestk = k; }
            if (k == kold) dfold_l = df;
        }
#pragma unroll
        for (int off = 16; off; off >>= 1) {
            float od = __shfl_down_sync(FULL, bestdf, off);
            int   ok = __shfl_down_sync(FULL, bestk, off);
            float oo = __shfl_down_sync(FULL, dfold_l, off);
            if (od < bestdf || (od == bestdf && ok < bestk)) { bestdf = od; bestk = ok; }
            dfold_l += oo;
        }
        if (lane == 0) {
            g_idx[b * TTOT + t] = bestk;
            g_ldelta[e] = bestdf - dfold_l;
        }
        __syncwarp();
    }
}

// ---- writer: gather-only quantize + indices ----
__global__ __launch_bounds__(256) void vq_write(float* __restrict__ out) {
    const int tid = threadIdx.x;
    const int b  = blockIdx.y;
    const int dz = blockIdx.z;
    const int t4 = (blockIdx.x * 256 + tid) << 2;

    const int4 kk = *(const int4*)&g_idx[b * TTOT + t4];

    if (dz == 0) {
        float4 fi = make_float4((float)kk.x, (float)kk.y, (float)kk.z, (float)kk.w);
        *(float4*)&out[Q_ELEMS + (size_t)b * TTOT + t4] = fi;
    }

    float* ob = out + (size_t)b * DD * TTOT + t4;
    const int dlo = dz * (DD / 4);
#pragma unroll 4
    for (int d = dlo; d < dlo + DD / 4; ++d) {
        const float* row = g_ct + d * KK;
        float4 q = make_float4(row[kk.x], row[kk.y], row[kk.z], row[kk.w]);
        *(float4*)&ob[(size_t)d * TTOT] = q;
    }
}

// ---- finalize ----
__global__ void vq_finalize(float* __restrict__ out) {
    __shared__ float s[256];
    int n = g_nflag;
    if (n > MAXF) n = MAXF;
    float a = 0.f;
    for (int j = threadIdx.x; j < NPART; j += 256) a += g_partials[j];
    for (int e = threadIdx.x; e < n; e += 256) a += g_ldelta[e];
    s[threadIdx.x] = a;
    __syncthreads();
    for (int st = 128; st > 0; st >>= 1) {
        if (threadIdx.x < st) s[threadIdx.x] += s[threadIdx.x + st];
        __syncthreads();
    }
    if (threadIdx.x == 0)
        out[Q_ELEMS + IDX_ELEMS] =
            0.25f * s[0] / (float)((size_t)BB * TTOT * DD);
}

extern "C" void kernel_launch(void* const* d_in, const int* in_sizes, int n_in,
                              void* d_out, int out_size) {
    const float* z  = (const float*)d_in[0];
    const float* cb = (const float*)d_in[1];
    float* out = (float*)d_out;

    cudaFuncSetAttribute(vq_main, cudaFuncAttributeMaxDynamicSharedMemorySize, SMEM_SZ);

    vq_prep<<<801, 256>>>(cb);
    dim3 grid(TTOT / TTILE, BB);
    vq_main<<<grid, 256, SMEM_SZ>>>(z);
    vq_refine<<<64, 128>>>(z, cb);
    dim3 wgrid(TTOT / 1024, BB, 4);
    vq_write<<<wgrid, 256>>>(out);
    vq_finalize<<<1, 256>>>(out);
}